// round 1
// baseline (speedup 1.0000x reference)
#include <cuda_runtime.h>

// Problem constants
#define HN   4
#define BN   2
#define CN   64
#define TN   2048
#define FN   64
#define HIDN 4
#define VDN  16
#define HBN  8       // H*B
#define DQK  256     // HID*F
#define DV   1024    // VD*F
#define EPSV 1e-5f

// Scratch (static device globals; allocation APIs are banned)
__device__ float g_Q[(size_t)HBN * TN * DQK];   //  16.8 MB
__device__ float g_K[(size_t)HBN * TN * DQK];   //  16.8 MB
__device__ float g_V[(size_t)HBN * TN * DV];    //  67.1 MB
__device__ float g_S[(size_t)HBN * TN * TN];    // 134.2 MB
__device__ float g_O[(size_t)HBN * TN * DV];    //  67.1 MB

__device__ __forceinline__ float warpSum(float v) {
    #pragma unroll
    for (int s = 16; s > 0; s >>= 1) v += __shfl_down_sync(0xffffffffu, v, s);
    return v;
}
__device__ __forceinline__ float warpMax(float v) {
    #pragma unroll
    for (int s = 16; s > 0; s >>= 1) v = fmaxf(v, __shfl_down_sync(0xffffffffu, v, s));
    return v;
}

// ---------------------------------------------------------------------------
// Kernel 1: fused QKV projection + PReLU + LayerNorm over (chan,freq)
// One block per (t, b). 256 threads: thread = (og = tid>>6 in 0..3, f = tid&63).
// Q/K: thread owns (o=og, f) for each head j.  V: thread owns (vd=og*4+m, f).
// ---------------------------------------------------------------------------
__global__ __launch_bounds__(256) void qkv_kernel(
    const float* __restrict__ x,
    const float* __restrict__ Wq, const float* __restrict__ bq, const float* __restrict__ aq,
    const float* __restrict__ gq, const float* __restrict__ betq,
    const float* __restrict__ Wk, const float* __restrict__ bk, const float* __restrict__ ak,
    const float* __restrict__ gk, const float* __restrict__ betk,
    const float* __restrict__ Wv, const float* __restrict__ bv, const float* __restrict__ av,
    const float* __restrict__ gv, const float* __restrict__ betv)
{
    __shared__ float xs[CN][FN];          // 16 KB
    __shared__ float wt[HN][CN][24];      // 24 KB: [og][c][w] w:0-3 Q, 4-7 K, 8-23 V
    __shared__ float rbuf[8][24];
    __shared__ float fin[24];

    const int t = blockIdx.x, b = blockIdx.y;
    const int tid = threadIdx.x;

    for (int i = tid; i < CN * FN; i += 256) {
        int c = i >> 6, f = i & 63;
        xs[c][f] = x[(((size_t)b * CN + c) * TN + t) * FN + f];
    }
    for (int i = tid; i < HN * CN * 24; i += 256) {
        int og = i / (CN * 24);
        int c  = (i / 24) % CN;
        int w  = i % 24;
        float val;
        if (w < 4)      val = Wq[(w * HIDN + og) * CN + c];
        else if (w < 8) val = Wk[((w - 4) * HIDN + og) * CN + c];
        else {
            int j = (w - 8) >> 2, m = (w - 8) & 3;
            val = Wv[(j * VDN + og * 4 + m) * CN + c];
        }
        wt[og][c][w] = val;
    }
    __syncthreads();

    const int f = tid & 63, og = tid >> 6;

    float accq[4], acck[4], accv[16];
    #pragma unroll
    for (int j = 0; j < 4; j++) { accq[j] = bq[j * HIDN + og]; acck[j] = bk[j * HIDN + og]; }
    #pragma unroll
    for (int j = 0; j < 4; j++)
        #pragma unroll
        for (int m = 0; m < 4; m++) accv[j * 4 + m] = bv[j * VDN + og * 4 + m];

    #pragma unroll 4
    for (int c = 0; c < CN; c++) {
        float xv = xs[c][f];
        const float4* wp4 = (const float4*)&wt[og][c][0];
        float w[24];
        *(float4*)&w[0]  = wp4[0];
        *(float4*)&w[4]  = wp4[1];
        *(float4*)&w[8]  = wp4[2];
        *(float4*)&w[12] = wp4[3];
        *(float4*)&w[16] = wp4[4];
        *(float4*)&w[20] = wp4[5];
        #pragma unroll
        for (int q = 0; q < 4; q++)  accq[q] = fmaf(w[q],      xv, accq[q]);
        #pragma unroll
        for (int q = 0; q < 4; q++)  acck[q] = fmaf(w[4 + q],  xv, acck[q]);
        #pragma unroll
        for (int q = 0; q < 16; q++) accv[q] = fmaf(w[8 + q],  xv, accv[q]);
    }

    // PReLU
    #pragma unroll
    for (int j = 0; j < 4; j++) {
        float a1 = aq[j], a2 = ak[j];
        accq[j] = accq[j] >= 0.f ? accq[j] : a1 * accq[j];
        acck[j] = acck[j] >= 0.f ? acck[j] : a2 * acck[j];
    }
    #pragma unroll
    for (int j = 0; j < 4; j++) {
        float a3 = av[j];
        #pragma unroll
        for (int m = 0; m < 4; m++) {
            float v = accv[j * 4 + m];
            accv[j * 4 + m] = v >= 0.f ? v : a3 * v;
        }
    }

    // per-head mean/var reductions: 12 groups (Q0-3, K0-3, V0-3), sum + sumsq
    float s[12], sq[12];
    #pragma unroll
    for (int j = 0; j < 4; j++) {
        s[j] = accq[j];       sq[j] = accq[j] * accq[j];
        s[4 + j] = acck[j];   sq[4 + j] = acck[j] * acck[j];
        float ps = 0.f, pq = 0.f;
        #pragma unroll
        for (int m = 0; m < 4; m++) { float v = accv[j * 4 + m]; ps += v; pq += v * v; }
        s[8 + j] = ps; sq[8 + j] = pq;
    }
    int lane = tid & 31, wid = tid >> 5;
    #pragma unroll
    for (int q = 0; q < 12; q++) {
        float a = warpSum(s[q]);
        float b2 = warpSum(sq[q]);
        if (lane == 0) { rbuf[wid][q] = a; rbuf[wid][12 + q] = b2; }
    }
    __syncthreads();
    if (tid < 24) {
        float a = 0.f;
        #pragma unroll
        for (int w2 = 0; w2 < 8; w2++) a += rbuf[w2][tid];
        fin[tid] = a;
    }
    __syncthreads();

    // normalize + store in attention layout
    #pragma unroll
    for (int j = 0; j < 4; j++) {
        float mu = fin[j] * (1.f / 256.f);
        float var = fin[12 + j] * (1.f / 256.f) - mu * mu;
        float rs = rsqrtf(var + EPSV);
        int gi = (j * HIDN + og) * FN + f;
        g_Q[(((size_t)(j * BN + b)) * TN + t) * DQK + og * FN + f] =
            (accq[j] - mu) * rs * gq[gi] + betq[gi];

        float muk = fin[4 + j] * (1.f / 256.f);
        float vark = fin[16 + j] * (1.f / 256.f) - muk * muk;
        float rsk = rsqrtf(vark + EPSV);
        g_K[(((size_t)(j * BN + b)) * TN + t) * DQK + og * FN + f] =
            (acck[j] - muk) * rsk * gk[gi] + betk[gi];
    }
    #pragma unroll
    for (int j = 0; j < 4; j++) {
        float mu = fin[8 + j] * (1.f / 1024.f);
        float var = fin[20 + j] * (1.f / 1024.f) - mu * mu;
        float rs = rsqrtf(var + EPSV);
        #pragma unroll
        for (int m = 0; m < 4; m++) {
            int vd = og * 4 + m;
            int gi = (j * VDN + vd) * FN + f;
            g_V[(((size_t)(j * BN + b)) * TN + t) * DV + vd * FN + f] =
                (accv[j * 4 + m] - mu) * rs * gv[gi] + betv[gi];
        }
    }
}

// ---------------------------------------------------------------------------
// Kernel 2: S = scale * Q * K^T   (per hb: 2048x2048x256, both row-major)
// 64x64 block tile, BK=16, 256 threads, 4x4 per thread
// ---------------------------------------------------------------------------
__global__ __launch_bounds__(256) void gemm_qk(float scale)
{
    __shared__ float As[16][68];
    __shared__ float Bs[16][68];
    const int hb = blockIdx.z;
    const int bm = blockIdx.y * 64, bn = blockIdx.x * 64;
    const float* A  = g_Q + (size_t)hb * TN * DQK;
    const float* Bm = g_K + (size_t)hb * TN * DQK;
    float* Cm       = g_S + (size_t)hb * TN * TN;

    const int tid = threadIdx.x;
    const int tx = tid & 15, ty = tid >> 4;
    const int lrow = tid >> 2, lk4 = tid & 3;

    float acc[4][4] = {};
    for (int k0 = 0; k0 < DQK; k0 += 16) {
        float4 a4 = *(const float4*)&A [(size_t)(bm + lrow) * DQK + k0 + lk4 * 4];
        float4 b4 = *(const float4*)&Bm[(size_t)(bn + lrow) * DQK + k0 + lk4 * 4];
        As[lk4 * 4 + 0][lrow] = a4.x; As[lk4 * 4 + 1][lrow] = a4.y;
        As[lk4 * 4 + 2][lrow] = a4.z; As[lk4 * 4 + 3][lrow] = a4.w;
        Bs[lk4 * 4 + 0][lrow] = b4.x; Bs[lk4 * 4 + 1][lrow] = b4.y;
        Bs[lk4 * 4 + 2][lrow] = b4.z; Bs[lk4 * 4 + 3][lrow] = b4.w;
        __syncthreads();
        #pragma unroll
        for (int kk = 0; kk < 16; kk++) {
            float a_[4], b_[4];
            *(float4*)a_ = *(const float4*)&As[kk][ty * 4];
            *(float4*)b_ = *(const float4*)&Bs[kk][tx * 4];
            #pragma unroll
            for (int i = 0; i < 4; i++)
                #pragma unroll
                for (int j = 0; j < 4; j++)
                    acc[i][j] = fmaf(a_[i], b_[j], acc[i][j]);
        }
        __syncthreads();
    }
    #pragma unroll
    for (int i = 0; i < 4; i++) {
        float4 o;
        o.x = acc[i][0] * scale; o.y = acc[i][1] * scale;
        o.z = acc[i][2] * scale; o.w = acc[i][3] * scale;
        *(float4*)&Cm[(size_t)(bm + ty * 4 + i) * TN + bn + tx * 4] = o;
    }
}

// ---------------------------------------------------------------------------
// Kernel 3: row softmax over g_S rows of length 2048; one block per row
// ---------------------------------------------------------------------------
__global__ __launch_bounds__(256) void softmax_kernel()
{
    const size_t row = blockIdx.x;
    float* p = g_S + row * TN;
    const int tid = threadIdx.x;
    const int lane = tid & 31, wid = tid >> 5;
    __shared__ float red[8];
    __shared__ float bmax, bsum;

    float v[8];
    float m = -1e30f;
    #pragma unroll
    for (int j = 0; j < 8; j++) { v[j] = p[tid + j * 256]; m = fmaxf(m, v[j]); }
    m = warpMax(m);
    if (lane == 0) red[wid] = m;
    __syncthreads();
    if (tid == 0) {
        float mm = red[0];
        #pragma unroll
        for (int w = 1; w < 8; w++) mm = fmaxf(mm, red[w]);
        bmax = mm;
    }
    __syncthreads();
    float M = bmax;
    float sum = 0.f;
    #pragma unroll
    for (int j = 0; j < 8; j++) { v[j] = expf(v[j] - M); sum += v[j]; }
    sum = warpSum(sum);
    if (lane == 0) red[wid] = sum;
    __syncthreads();
    if (tid == 0) {
        float ss = 0.f;
        #pragma unroll
        for (int w = 0; w < 8; w++) ss += red[w];
        bsum = ss;
    }
    __syncthreads();
    float r = 1.f / bsum;
    #pragma unroll
    for (int j = 0; j < 8; j++) p[tid + j * 256] = v[j] * r;
}

// ---------------------------------------------------------------------------
// Kernel 4: O = P * V  (per hb: 2048x1024x2048, A row-major, B row-major)
// ---------------------------------------------------------------------------
__global__ __launch_bounds__(256) void gemm_pv()
{
    __shared__ float As[16][68];
    __shared__ float Bs[16][68];
    const int hb = blockIdx.z;
    const int bm = blockIdx.y * 64, bn = blockIdx.x * 64;
    const float* A  = g_S + (size_t)hb * TN * TN;
    const float* Bm = g_V + (size_t)hb * TN * DV;
    float* Cm       = g_O + (size_t)hb * TN * DV;

    const int tid = threadIdx.x;
    const int tx = tid & 15, ty = tid >> 4;
    const int lrow = tid >> 2, lk4 = tid & 3;   // A load
    const int brow = tid >> 4, bc4 = tid & 15;  // B load

    float acc[4][4] = {};
    for (int k0 = 0; k0 < TN; k0 += 16) {
        float4 a4 = *(const float4*)&A[(size_t)(bm + lrow) * TN + k0 + lk4 * 4];
        As[lk4 * 4 + 0][lrow] = a4.x; As[lk4 * 4 + 1][lrow] = a4.y;
        As[lk4 * 4 + 2][lrow] = a4.z; As[lk4 * 4 + 3][lrow] = a4.w;
        float4 b4 = *(const float4*)&Bm[(size_t)(k0 + brow) * DV + bn + bc4 * 4];
        *(float4*)&Bs[brow][bc4 * 4] = b4;
        __syncthreads();
        #pragma unroll
        for (int kk = 0; kk < 16; kk++) {
            float a_[4], b_[4];
            *(float4*)a_ = *(const float4*)&As[kk][ty * 4];
            *(float4*)b_ = *(const float4*)&Bs[kk][tx * 4];
            #pragma unroll
            for (int i = 0; i < 4; i++)
                #pragma unroll
                for (int j = 0; j < 4; j++)
                    acc[i][j] = fmaf(a_[i], b_[j], acc[i][j]);
        }
        __syncthreads();
    }
    #pragma unroll
    for (int i = 0; i < 4; i++) {
        float4 o;
        o.x = acc[i][0]; o.y = acc[i][1]; o.z = acc[i][2]; o.w = acc[i][3];
        *(float4*)&Cm[(size_t)(bm + ty * 4 + i) * DV + bn + tx * 4] = o;
    }
}

// ---------------------------------------------------------------------------
// Kernel 5: out = LN(PReLU(Wp @ concat(O) + bp)) + x   per (b,t)
// ---------------------------------------------------------------------------
__global__ __launch_bounds__(256) void outproj_kernel(
    const float* __restrict__ x, const float* __restrict__ Wp, const float* __restrict__ bp,
    const float* __restrict__ ap, const float* __restrict__ gp, const float* __restrict__ betp,
    float* __restrict__ out)
{
    __shared__ float Oc[CN][FN];        // 16 KB
    __shared__ float wt[4][CN][16];     // 16 KB: [og][c][m]  (o = og*16+m)
    __shared__ float rbuf[8][2];
    __shared__ float fin2[2];

    const int t = blockIdx.x, b = blockIdx.y;
    const int tid = threadIdx.x;

    for (int i = tid; i < CN * FN; i += 256) {
        int c = i >> 6, f = i & 63;
        int h = c >> 4, vd = c & 15;
        Oc[c][f] = g_O[(((size_t)(h * BN + b)) * TN + t) * DV + vd * FN + f];
    }
    for (int i = tid; i < 4 * CN * 16; i += 256) {
        int og = i / (CN * 16), c = (i >> 4) % CN, m = i & 15;
        wt[og][c][m] = Wp[(og * 16 + m) * CN + c];
    }
    __syncthreads();

    const int f = tid & 63, og = tid >> 6;
    float acc[16];
    #pragma unroll
    for (int m = 0; m < 16; m++) acc[m] = bp[og * 16 + m];

    #pragma unroll 4
    for (int c = 0; c < CN; c++) {
        float xv = Oc[c][f];
        const float4* wp4 = (const float4*)&wt[og][c][0];
        float w[16];
        *(float4*)&w[0]  = wp4[0];
        *(float4*)&w[4]  = wp4[1];
        *(float4*)&w[8]  = wp4[2];
        *(float4*)&w[12] = wp4[3];
        #pragma unroll
        for (int m = 0; m < 16; m++) acc[m] = fmaf(w[m], xv, acc[m]);
    }

    float a = ap[0];
    float ps = 0.f, pq = 0.f;
    #pragma unroll
    for (int m = 0; m < 16; m++) {
        float v = acc[m];
        v = v >= 0.f ? v : a * v;
        acc[m] = v;
        ps += v; pq += v * v;
    }
    int lane = tid & 31, wid = tid >> 5;
    ps = warpSum(ps); pq = warpSum(pq);
    if (lane == 0) { rbuf[wid][0] = ps; rbuf[wid][1] = pq; }
    __syncthreads();
    if (tid == 0) {
        float s0 = 0.f, s1 = 0.f;
        #pragma unroll
        for (int w = 0; w < 8; w++) { s0 += rbuf[w][0]; s1 += rbuf[w][1]; }
        fin2[0] = s0; fin2[1] = s1;
    }
    __syncthreads();
    float mu = fin2[0] * (1.f / 4096.f);
    float var = fin2[1] * (1.f / 4096.f) - mu * mu;
    float rs = rsqrtf(var + EPSV);

    #pragma unroll
    for (int m = 0; m < 16; m++) {
        int o = og * 16 + m;
        float v = (acc[m] - mu) * rs * gp[o * FN + f] + betp[o * FN + f];
        size_t idx = (((size_t)b * CN + o) * TN + t) * FN + f;
        out[idx] = v + x[idx];
    }
}

// ---------------------------------------------------------------------------
extern "C" void kernel_launch(void* const* d_in, const int* in_sizes, int n_in,
                              void* d_out, int out_size)
{
    const float* x    = (const float*)d_in[0];
    const float* Wq   = (const float*)d_in[1];
    const float* bq   = (const float*)d_in[2];
    const float* aq   = (const float*)d_in[3];
    const float* gq   = (const float*)d_in[4];
    const float* betq = (const float*)d_in[5];
    const float* Wk   = (const float*)d_in[6];
    const float* bk   = (const float*)d_in[7];
    const float* ak   = (const float*)d_in[8];
    const float* gk   = (const float*)d_in[9];
    const float* betk = (const float*)d_in[10];
    const float* Wv   = (const float*)d_in[11];
    const float* bv   = (const float*)d_in[12];
    const float* av   = (const float*)d_in[13];
    const float* gv   = (const float*)d_in[14];
    const float* betv = (const float*)d_in[15];
    const float* Wp   = (const float*)d_in[16];
    const float* bp   = (const float*)d_in[17];
    const float* ap   = (const float*)d_in[18];
    const float* gp   = (const float*)d_in[19];
    const float* betp = (const float*)d_in[20];
    float* out = (float*)d_out;

    qkv_kernel<<<dim3(TN, BN), 256>>>(x, Wq, bq, aq, gq, betq,
                                      Wk, bk, ak, gk, betk,
                                      Wv, bv, av, gv, betv);
    gemm_qk<<<dim3(TN / 64, TN / 64, HBN), 256>>>(0.0625f);  // 1/sqrt(256)
    softmax_kernel<<<HBN * TN, 256>>>();
    gemm_pv<<<dim3(DV / 64, TN / 64, HBN), 256>>>();
    outproj_kernel<<<dim3(TN, BN), 256>>>(x, Wp, bp, ap, gp, betp, out);
}

// round 2
// speedup vs baseline: 2.4536x; 2.4536x over previous
#include <cuda_runtime.h>
#include <cstdint>

// Problem constants
#define HN   4
#define BN   2
#define CN   64
#define TN   2048
#define FN   64
#define HIDN 4
#define VDN  16
#define HBN  8       // H*B
#define DQK  256     // HID*F
#define DV   1024    // VD*F
#define EPSV 1e-5f

// Scratch (static device globals; allocation APIs are banned)
__device__ float g_Q [(size_t)HBN * TN * DQK];   //  16.8 MB (tf32-rounded, pre-scaled)
__device__ float g_Kt[(size_t)HBN * DQK * TN];   //  16.8 MB (tf32-rounded, d-major)
__device__ float g_V [(size_t)HBN * TN * DV];    //  67.1 MB (tf32-rounded)
__device__ float g_S [(size_t)HBN * TN * TN];    // 134.2 MB (fp32 logits -> tf32 probs)
__device__ float g_O [(size_t)HBN * TN * DV];    //  67.1 MB (fp32)

__device__ __forceinline__ float warpSum(float v) {
    #pragma unroll
    for (int s = 16; s > 0; s >>= 1) v += __shfl_down_sync(0xffffffffu, v, s);
    return v;
}
__device__ __forceinline__ float warpMax(float v) {
    #pragma unroll
    for (int s = 16; s > 0; s >>= 1) v = fmaxf(v, __shfl_down_sync(0xffffffffu, v, s));
    return v;
}
__device__ __forceinline__ uint32_t f2tf32(float x) {
    uint32_t u;
    asm("cvt.rna.tf32.f32 %0, %1;" : "=r"(u) : "f"(x));
    return u;
}
__device__ __forceinline__ float tf32f(float x) { return __uint_as_float(f2tf32(x)); }

__device__ __forceinline__ void cpasync16(uint32_t dst, const void* src) {
    asm volatile("cp.async.cg.shared.global [%0], [%1], 16;" :: "r"(dst), "l"(src));
}

#define MMA_TF32(d, a, b)                                                     \
    asm volatile(                                                             \
        "mma.sync.aligned.m16n8k8.row.col.f32.tf32.tf32.f32 "                 \
        "{%0,%1,%2,%3}, {%4,%5,%6,%7}, {%8,%9}, {%0,%1,%2,%3};"               \
        : "+f"((d)[0]), "+f"((d)[1]), "+f"((d)[2]), "+f"((d)[3])              \
        : "r"((a)[0]), "r"((a)[1]), "r"((a)[2]), "r"((a)[3]),                 \
          "r"((b)[0]), "r"((b)[1]))

// ---------------------------------------------------------------------------
// Kernel 1: fused QKV projection + PReLU + LayerNorm over (chan,freq)
// One block per (t, b). 256 threads: thread = (og = tid>>6 in 0..3, f = tid&63).
// Writes Q pre-scaled by 1/sqrt(dqk), all outputs rounded to tf32.
// K written transposed (d-major) for the QK GEMM's cp.async path.
// ---------------------------------------------------------------------------
__global__ __launch_bounds__(256) void qkv_kernel(
    const float* __restrict__ x,
    const float* __restrict__ Wq, const float* __restrict__ bq, const float* __restrict__ aq,
    const float* __restrict__ gq, const float* __restrict__ betq,
    const float* __restrict__ Wk, const float* __restrict__ bk, const float* __restrict__ ak,
    const float* __restrict__ gk, const float* __restrict__ betk,
    const float* __restrict__ Wv, const float* __restrict__ bv, const float* __restrict__ av,
    const float* __restrict__ gv, const float* __restrict__ betv)
{
    __shared__ float xs[CN][FN];
    __shared__ float wt[HN][CN][24];
    __shared__ float rbuf[8][24];
    __shared__ float fin[24];

    const int t = blockIdx.x, b = blockIdx.y;
    const int tid = threadIdx.x;

    for (int i = tid; i < CN * FN; i += 256) {
        int c = i >> 6, f = i & 63;
        xs[c][f] = x[(((size_t)b * CN + c) * TN + t) * FN + f];
    }
    for (int i = tid; i < HN * CN * 24; i += 256) {
        int og = i / (CN * 24);
        int c  = (i / 24) % CN;
        int w  = i % 24;
        float val;
        if (w < 4)      val = Wq[(w * HIDN + og) * CN + c];
        else if (w < 8) val = Wk[((w - 4) * HIDN + og) * CN + c];
        else {
            int j = (w - 8) >> 2, m = (w - 8) & 3;
            val = Wv[(j * VDN + og * 4 + m) * CN + c];
        }
        wt[og][c][w] = val;
    }
    __syncthreads();

    const int f = tid & 63, og = tid >> 6;

    float accq[4], acck[4], accv[16];
    #pragma unroll
    for (int j = 0; j < 4; j++) { accq[j] = bq[j * HIDN + og]; acck[j] = bk[j * HIDN + og]; }
    #pragma unroll
    for (int j = 0; j < 4; j++)
        #pragma unroll
        for (int m = 0; m < 4; m++) accv[j * 4 + m] = bv[j * VDN + og * 4 + m];

    #pragma unroll 4
    for (int c = 0; c < CN; c++) {
        float xv = xs[c][f];
        const float4* wp4 = (const float4*)&wt[og][c][0];
        float w[24];
        *(float4*)&w[0]  = wp4[0];
        *(float4*)&w[4]  = wp4[1];
        *(float4*)&w[8]  = wp4[2];
        *(float4*)&w[12] = wp4[3];
        *(float4*)&w[16] = wp4[4];
        *(float4*)&w[20] = wp4[5];
        #pragma unroll
        for (int q = 0; q < 4; q++)  accq[q] = fmaf(w[q],      xv, accq[q]);
        #pragma unroll
        for (int q = 0; q < 4; q++)  acck[q] = fmaf(w[4 + q],  xv, acck[q]);
        #pragma unroll
        for (int q = 0; q < 16; q++) accv[q] = fmaf(w[8 + q],  xv, accv[q]);
    }

    // PReLU
    #pragma unroll
    for (int j = 0; j < 4; j++) {
        float a1 = aq[j], a2 = ak[j];
        accq[j] = accq[j] >= 0.f ? accq[j] : a1 * accq[j];
        acck[j] = acck[j] >= 0.f ? acck[j] : a2 * acck[j];
    }
    #pragma unroll
    for (int j = 0; j < 4; j++) {
        float a3 = av[j];
        #pragma unroll
        for (int m = 0; m < 4; m++) {
            float v = accv[j * 4 + m];
            accv[j * 4 + m] = v >= 0.f ? v : a3 * v;
        }
    }

    // per-head mean/var reductions
    float s[12], sq[12];
    #pragma unroll
    for (int j = 0; j < 4; j++) {
        s[j] = accq[j];       sq[j] = accq[j] * accq[j];
        s[4 + j] = acck[j];   sq[4 + j] = acck[j] * acck[j];
        float ps = 0.f, pq = 0.f;
        #pragma unroll
        for (int m = 0; m < 4; m++) { float v = accv[j * 4 + m]; ps += v; pq += v * v; }
        s[8 + j] = ps; sq[8 + j] = pq;
    }
    int lane = tid & 31, wid = tid >> 5;
    #pragma unroll
    for (int q = 0; q < 12; q++) {
        float a = warpSum(s[q]);
        float b2 = warpSum(sq[q]);
        if (lane == 0) { rbuf[wid][q] = a; rbuf[wid][12 + q] = b2; }
    }
    __syncthreads();
    if (tid < 24) {
        float a = 0.f;
        #pragma unroll
        for (int w2 = 0; w2 < 8; w2++) a += rbuf[w2][tid];
        fin[tid] = a;
    }
    __syncthreads();

    const float QSCALE = 0.0625f;  // 1/sqrt(256), folded into Q

    #pragma unroll
    for (int j = 0; j < 4; j++) {
        float mu = fin[j] * (1.f / 256.f);
        float var = fin[12 + j] * (1.f / 256.f) - mu * mu;
        float rs = rsqrtf(var + EPSV);
        int gi = (j * HIDN + og) * FN + f;
        float qv = ((accq[j] - mu) * rs * gq[gi] + betq[gi]) * QSCALE;
        g_Q[(((size_t)(j * BN + b)) * TN + t) * DQK + og * FN + f] = tf32f(qv);

        float muk = fin[4 + j] * (1.f / 256.f);
        float vark = fin[16 + j] * (1.f / 256.f) - muk * muk;
        float rsk = rsqrtf(vark + EPSV);
        float kv = (acck[j] - muk) * rsk * gk[gi] + betk[gi];
        // transposed layout: (hb, d, t)
        g_Kt[(((size_t)(j * BN + b)) * DQK + og * FN + f) * TN + t] = tf32f(kv);
    }
    #pragma unroll
    for (int j = 0; j < 4; j++) {
        float mu = fin[8 + j] * (1.f / 1024.f);
        float var = fin[20 + j] * (1.f / 1024.f) - mu * mu;
        float rs = rsqrtf(var + EPSV);
        #pragma unroll
        for (int m = 0; m < 4; m++) {
            int vd = og * 4 + m;
            int gi = (j * VDN + vd) * FN + f;
            float vv = (accv[j * 4 + m] - mu) * rs * gv[gi] + betv[gi];
            g_V[(((size_t)(j * BN + b)) * TN + t) * DV + vd * FN + f] = tf32f(vv);
        }
    }
}

// ---------------------------------------------------------------------------
// Kernel 2/4: TF32 tensor-core GEMM, 128x128x16 tiles, double-buffered cp.async.
// MODE 0: S = Q * Kt            (M=T, N=T,  K=DQK)
// MODE 1: O = P * V             (M=T, N=DV, K=T)
// A row-major (M x K), B stored (K x N) row-major, C row-major (M x N).
// 256 threads = 8 warps, warp tile 32x64 (4x2 warp grid), m16n8k8 tf32 mma.
// ---------------------------------------------------------------------------
template<int MODE>
__global__ __launch_bounds__(256) void gemm_tc()
{
    constexpr int LDA  = (MODE == 0) ? DQK : TN;
    constexpr int LDB  = (MODE == 0) ? TN  : DV;
    constexpr int LDC  = (MODE == 0) ? TN  : DV;
    constexpr int KTOT = (MODE == 0) ? DQK : TN;
    constexpr int NT   = KTOT / 16;
    constexpr int ASTR = 20;    // As row stride (floats)
    constexpr int BSTR = 136;   // Bs row stride (floats)

    __shared__ float As[2][128 * ASTR];
    __shared__ float Bs[2][16 * BSTR];

    const int hb = blockIdx.z;
    const float* A = (MODE == 0 ? g_Q : g_S)
                   + (size_t)hb * TN * LDA + (size_t)blockIdx.y * 128 * LDA;
    const float* B = (MODE == 0 ? g_Kt : g_V)
                   + (size_t)hb * KTOT * LDB + blockIdx.x * 128;
    float* C = (MODE == 0 ? g_S : g_O)
             + (size_t)hb * TN * LDC + (size_t)blockIdx.y * 128 * LDC + blockIdx.x * 128;

    const int tid = threadIdx.x;
    const int lane = tid & 31, w = tid >> 5;
    const int wm = (w & 3) * 32, wn = (w >> 2) * 64;
    const int r = lane >> 2, cq = lane & 3;

    const int arow = tid >> 1,  akseg = (tid & 1) * 8;
    const int brow = tid >> 4,  bnseg = (tid & 15) * 8;

    const uint32_t asA = (uint32_t)__cvta_generic_to_shared(&As[0][0]);
    const uint32_t asB = (uint32_t)__cvta_generic_to_shared(&Bs[0][0]);

    auto issue = [&](int it, int buf) {
        const float* ap = A + (size_t)arow * LDA + it * 16 + akseg;
        uint32_t ad = asA + (uint32_t)(buf * 128 * ASTR + arow * ASTR + akseg) * 4u;
        cpasync16(ad, ap);
        cpasync16(ad + 16u, ap + 4);
        const float* bp = B + (size_t)(it * 16 + brow) * LDB + bnseg;
        uint32_t bd = asB + (uint32_t)(buf * 16 * BSTR + brow * BSTR + bnseg) * 4u;
        cpasync16(bd, bp);
        cpasync16(bd + 16u, bp + 4);
        asm volatile("cp.async.commit_group;");
    };

    float acc[2][8][4];
    #pragma unroll
    for (int mi = 0; mi < 2; mi++)
        #pragma unroll
        for (int ni = 0; ni < 8; ni++)
            #pragma unroll
            for (int q = 0; q < 4; q++) acc[mi][ni][q] = 0.f;

    issue(0, 0);
    for (int it = 0; it < NT; ++it) {
        const int cur = it & 1;
        if (it + 1 < NT) {
            issue(it + 1, cur ^ 1);
            asm volatile("cp.async.wait_group 1;");
        } else {
            asm volatile("cp.async.wait_group 0;");
        }
        __syncthreads();

        const float* Asb = &As[cur][0];
        const float* Bsb = &Bs[cur][0];
        #pragma unroll
        for (int kk = 0; kk < 16; kk += 8) {
            uint32_t af[2][4];
            #pragma unroll
            for (int mi = 0; mi < 2; mi++) {
                const int mrow = wm + mi * 16;
                af[mi][0] = __float_as_uint(Asb[(mrow + r)     * ASTR + kk + cq]);
                af[mi][1] = __float_as_uint(Asb[(mrow + r + 8) * ASTR + kk + cq]);
                af[mi][2] = __float_as_uint(Asb[(mrow + r)     * ASTR + kk + cq + 4]);
                af[mi][3] = __float_as_uint(Asb[(mrow + r + 8) * ASTR + kk + cq + 4]);
            }
            uint32_t bf[8][2];
            #pragma unroll
            for (int ni = 0; ni < 8; ni++) {
                const int ncol = wn + ni * 8 + r;
                bf[ni][0] = __float_as_uint(Bsb[(kk + cq)     * BSTR + ncol]);
                bf[ni][1] = __float_as_uint(Bsb[(kk + cq + 4) * BSTR + ncol]);
            }
            #pragma unroll
            for (int mi = 0; mi < 2; mi++)
                #pragma unroll
                for (int ni = 0; ni < 8; ni++)
                    MMA_TF32(acc[mi][ni], af[mi], bf[ni]);
        }
        __syncthreads();
    }

    #pragma unroll
    for (int mi = 0; mi < 2; mi++) {
        const int row0 = wm + mi * 16 + r;
        #pragma unroll
        for (int ni = 0; ni < 8; ni++) {
            const int col = wn + ni * 8 + cq * 2;
            float2 v0 = make_float2(acc[mi][ni][0], acc[mi][ni][1]);
            float2 v1 = make_float2(acc[mi][ni][2], acc[mi][ni][3]);
            *(float2*)&C[(size_t)row0 * LDC + col]       = v0;
            *(float2*)&C[(size_t)(row0 + 8) * LDC + col] = v1;
        }
    }
}

// ---------------------------------------------------------------------------
// Kernel 3: row softmax over g_S rows of length 2048; one block per row.
// Output rounded to tf32 (feeds the PV tensor-core GEMM).
// ---------------------------------------------------------------------------
__global__ __launch_bounds__(256) void softmax_kernel()
{
    const size_t row = blockIdx.x;
    float* p = g_S + row * TN;
    const int tid = threadIdx.x;
    const int lane = tid & 31, wid = tid >> 5;
    __shared__ float red[8];
    __shared__ float bmax, bsum;

    float v[8];
    float m = -1e30f;
    #pragma unroll
    for (int j = 0; j < 8; j++) { v[j] = p[tid + j * 256]; m = fmaxf(m, v[j]); }
    m = warpMax(m);
    if (lane == 0) red[wid] = m;
    __syncthreads();
    if (tid == 0) {
        float mm = red[0];
        #pragma unroll
        for (int w = 1; w < 8; w++) mm = fmaxf(mm, red[w]);
        bmax = mm;
    }
    __syncthreads();
    float M = bmax;
    float sum = 0.f;
    #pragma unroll
    for (int j = 0; j < 8; j++) { v[j] = __expf(v[j] - M); sum += v[j]; }
    sum = warpSum(sum);
    if (lane == 0) red[wid] = sum;
    __syncthreads();
    if (tid == 0) {
        float ss = 0.f;
        #pragma unroll
        for (int w = 0; w < 8; w++) ss += red[w];
        bsum = ss;
    }
    __syncthreads();
    float r = 1.f / bsum;
    #pragma unroll
    for (int j = 0; j < 8; j++) p[tid + j * 256] = tf32f(v[j] * r);
}

// ---------------------------------------------------------------------------
// Kernel 5: out = LN(PReLU(Wp @ concat(O) + bp)) + x   per (b,t)
// ---------------------------------------------------------------------------
__global__ __launch_bounds__(256) void outproj_kernel(
    const float* __restrict__ x, const float* __restrict__ Wp, const float* __restrict__ bp,
    const float* __restrict__ ap, const float* __restrict__ gp, const float* __restrict__ betp,
    float* __restrict__ out)
{
    __shared__ float Oc[CN][FN];
    __shared__ float wt[4][CN][16];
    __shared__ float rbuf[8][2];
    __shared__ float fin2[2];

    const int t = blockIdx.x, b = blockIdx.y;
    const int tid = threadIdx.x;

    for (int i = tid; i < CN * FN; i += 256) {
        int c = i >> 6, f = i & 63;
        int h = c >> 4, vd = c & 15;
        Oc[c][f] = g_O[(((size_t)(h * BN + b)) * TN + t) * DV + vd * FN + f];
    }
    for (int i = tid; i < 4 * CN * 16; i += 256) {
        int og = i / (CN * 16), c = (i >> 4) % CN, m = i & 15;
        wt[og][c][m] = Wp[(og * 16 + m) * CN + c];
    }
    __syncthreads();

    const int f = tid & 63, og = tid >> 6;
    float acc[16];
    #pragma unroll
    for (int m = 0; m < 16; m++) acc[m] = bp[og * 16 + m];

    #pragma unroll 4
    for (int c = 0; c < CN; c++) {
        float xv = Oc[c][f];
        const float4* wp4 = (const float4*)&wt[og][c][0];
        float w[16];
        *(float4*)&w[0]  = wp4[0];
        *(float4*)&w[4]  = wp4[1];
        *(float4*)&w[8]  = wp4[2];
        *(float4*)&w[12] = wp4[3];
        #pragma unroll
        for (int m = 0; m < 16; m++) acc[m] = fmaf(w[m], xv, acc[m]);
    }

    float a = ap[0];
    float ps = 0.f, pq = 0.f;
    #pragma unroll
    for (int m = 0; m < 16; m++) {
        float v = acc[m];
        v = v >= 0.f ? v : a * v;
        acc[m] = v;
        ps += v; pq += v * v;
    }
    int lane = tid & 31, wid = tid >> 5;
    ps = warpSum(ps); pq = warpSum(pq);
    if (lane == 0) { rbuf[wid][0] = ps; rbuf[wid][1] = pq; }
    __syncthreads();
    if (tid == 0) {
        float s0 = 0.f, s1 = 0.f;
        #pragma unroll
        for (int w = 0; w < 8; w++) { s0 += rbuf[w][0]; s1 += rbuf[w][1]; }
        fin2[0] = s0; fin2[1] = s1;
    }
    __syncthreads();
    float mu = fin2[0] * (1.f / 4096.f);
    float var = fin2[1] * (1.f / 4096.f) - mu * mu;
    float rs = rsqrtf(var + EPSV);

    #pragma unroll
    for (int m = 0; m < 16; m++) {
        int o = og * 16 + m;
        float v = (acc[m] - mu) * rs * gp[o * FN + f] + betp[o * FN + f];
        size_t idx = (((size_t)b * CN + o) * TN + t) * FN + f;
        out[idx] = v + x[idx];
    }
}

// ---------------------------------------------------------------------------
extern "C" void kernel_launch(void* const* d_in, const int* in_sizes, int n_in,
                              void* d_out, int out_size)
{
    const float* x    = (const float*)d_in[0];
    const float* Wq   = (const float*)d_in[1];
    const float* bq   = (const float*)d_in[2];
    const float* aq   = (const float*)d_in[3];
    const float* gq   = (const float*)d_in[4];
    const float* betq = (const float*)d_in[5];
    const float* Wk   = (const float*)d_in[6];
    const float* bk   = (const float*)d_in[7];
    const float* ak   = (const float*)d_in[8];
    const float* gk   = (const float*)d_in[9];
    const float* betk = (const float*)d_in[10];
    const float* Wv   = (const float*)d_in[11];
    const float* bv   = (const float*)d_in[12];
    const float* av   = (const float*)d_in[13];
    const float* gv   = (const float*)d_in[14];
    const float* betv = (const float*)d_in[15];
    const float* Wp   = (const float*)d_in[16];
    const float* bp   = (const float*)d_in[17];
    const float* ap   = (const float*)d_in[18];
    const float* gp   = (const float*)d_in[19];
    const float* betp = (const float*)d_in[20];
    float* out = (float*)d_out;

    qkv_kernel<<<dim3(TN, BN), 256>>>(x, Wq, bq, aq, gq, betq,
                                      Wk, bk, ak, gk, betk,
                                      Wv, bv, av, gv, betv);
    gemm_tc<0><<<dim3(TN / 128, TN / 128, HBN), 256>>>();   // S = Q*K^T (scale folded)
    softmax_kernel<<<HBN * TN, 256>>>();
    gemm_tc<1><<<dim3(DV / 128, TN / 128, HBN), 256>>>();   // O = P*V
    outproj_kernel<<<dim3(TN, BN), 256>>>(x, Wp, bp, ap, gp, betp, out);
}